// round 11
// baseline (speedup 1.0000x reference)
#include <cuda_runtime.h>
#include <math.h>

#define B 16
#define N 32
#define C 512
#define FEAT 224

#define HW0 784
#define HW1 196
#define HW2 49
#define OUT_ROW (C*(HW0+HW1+HW2))
#define OUT_OFF1 (C*HW0)         // 401408
#define OUT_OFF2 (C*(HW0+HW1))   // 501760
#define MAXSEG 96
#define GRID_P 384               // 8 blocks per (l,b) group; provably co-resident

// ---------------- scratch (no allocations allowed) ----------------
__device__ float    g_wx[B][MAXSEG];
__device__ unsigned g_colm[B][MAXSEG];
__device__ int      g_cellx[B][MAXSEG];
__device__ int      g_nsegx[B];
__device__ float    g_sum28[B][HW0];   // per-8x8-tile sum of sigmoid
__device__ float    g_logits[3 * B * C];
__device__ unsigned g_bar;             // monotonic grid-barrier counter

// ---------------- K0: per-batch x-segment table (x-axis only) -----------
__global__ void seg_kernel(const float* __restrict__ boxes) {
    int b = blockIdx.x;
    int t = threadIdx.x;
    int lane = t & 31, wl = t >> 5;

    __shared__ int sbx[N * 4];
    __shared__ unsigned char flag[FEAT];
    __shared__ int segstart[MAXSEG];
    __shared__ int woff[8];
    __shared__ int snseg;

    if (t < N * 4) sbx[t] = (int)floorf(boxes[b * N * 4 + t] * (float)FEAT);
    flag[t] = ((t & 7) == 0);
    __syncthreads();

    if (t < N) {
        int e1 = sbx[4 * t], e2 = sbx[4 * t + 2];
        if (e1 >= 0 && e1 < FEAT) flag[e1] = 1;
        if (e2 >= 0 && e2 < FEAT) flag[e2] = 1;
    }
    __syncthreads();

    unsigned bal = __ballot_sync(0xffffffffu, flag[t] != 0);
    if (lane == 0) woff[wl] = __popc(bal);
    __syncthreads();
    if (t == 0) {
        int run = 0;
        for (int i = 0; i < 7; i++) { int c = woff[i]; woff[i] = run; run += c; }
        snseg = run;
    }
    __syncthreads();
    if (flag[t])
        segstart[woff[wl] + __popc(bal & ((1u << lane) - 1u))] = t;
    __syncthreads();

    int nseg = snseg;
    if (t < nseg) {
        int s = segstart[t];
        int wd = ((t + 1 < nseg) ? segstart[t + 1] : FEAT) - s;
        unsigned m = 0;
#pragma unroll
        for (int n = 0; n < N; n++)
            m |= (unsigned)(s >= sbx[4 * n] && s < sbx[4 * n + 2]) << n;
        g_wx[b][t] = (float)wd;
        g_colm[b][t] = m;
        g_cellx[b][t] = s >> 3;
    }
    if (t == 0) g_nsegx[b] = nseg;
}

// ---------------- K1: rectangle eval -> 8x8 tile sums ------------------
__global__ void tile_kernel(const float* __restrict__ confs,
                            const float* __restrict__ boxes) {
    int band = blockIdx.x, b = blockIdx.y;
    int t = threadIdx.x;
    __shared__ int sbx[N * 4];
    __shared__ float swx[MAXSEG];
    __shared__ unsigned scolm[MAXSEG];
    __shared__ int scell[MAXSEG];
    __shared__ unsigned rm8[8];
    __shared__ float swy[8];
    __shared__ unsigned srowm[8];
    __shared__ float sconf[N];
    __shared__ float stile[28];
    __shared__ int snx, sny;

    if (t < N * 4) sbx[t] = (int)floorf(boxes[b * N * 4 + t] * (float)FEAT);
    if (t < N) sconf[t] = confs[b * N + t];
    if (t == 0) snx = g_nsegx[b];
    if (t < 28) stile[t] = 0.f;
    __syncthreads();

    if (t < 8) {
        int y = band * 8 + t;
        unsigned rm = 0;
#pragma unroll
        for (int n = 0; n < N; n++)
            rm |= (unsigned)(y >= sbx[4 * n + 1] && y < sbx[4 * n + 3]) << n;
        rm8[t] = rm;
    }
    int nx = snx;
    for (int i = t; i < nx; i += 256) {
        swx[i] = g_wx[b][i];
        scolm[i] = g_colm[b][i];
        scell[i] = g_cellx[b][i];
    }
    __syncthreads();
    if (t == 0) {            // merge equal adjacent row masks
        int ny = 0;
        for (int i = 0; i < 8; i++) {
            if (i == 0 || rm8[i] != rm8[i - 1]) {
                srowm[ny] = rm8[i];
                swy[ny] = 1.f;
                ny++;
            } else {
                swy[ny - 1] += 1.f;
            }
        }
        sny = ny;
    }
    __syncthreads();

    int ny = sny;
    int pairs = nx * ny;
    for (int p = t; p < pairs; p += 256) {
        int ys = p / nx, xs = p - ys * nx;
        unsigned m = srowm[ys] & scolm[xs];
        float v = 0.f;
        while (m) {
            int i = __ffs(m) - 1;
            v += sconf[i];
            m &= m - 1;
        }
        float sg = __fdividef(1.f, 1.f + __expf(-v));
        atomicAdd(&stile[scell[xs]], swy[ys] * swx[xs] * sg);
    }
    __syncthreads();
    if (t < 28) g_sum28[b][band * 28 + t] = stile[t];
}

// -------- K2: persistent fused logits + softmax + scale ------------------
// grid = 384 blocks x 256 threads. Block bid: group g = bid/8 = (l,b),
// chunk = bid%8; rows c = chunk*64 + warp*8 + j (8 rows/warp).
// Phase1: logits kept in registers. Grid barrier. Per-block group softmax
// reduction. Phase2: scale + store.
__global__ void __launch_bounds__(256, 4)
fused_kernel(const float* __restrict__ f0,
             const float* __restrict__ f1,
             const float* __restrict__ f2,
             float* __restrict__ out) {
    int bid = blockIdx.x;
    int g = bid >> 3, chunk = bid & 7;
    int l = g >> 4, b = g & 15;
    int t = threadIdx.x, warp = t >> 5, lane = t & 31;

    __shared__ __align__(16) float satt[HW0];
    const float* gs = g_sum28[b];

    // ---- build att for this group's level ----
    if (l == 0) {
        for (int i = t; i < HW0; i += 256) satt[i] = gs[i] * (1.f / 64.f);
    } else if (l == 1) {
        if (t < HW1) {
            int ay = t / 14, ax = t % 14;
            int base = (2 * ay) * 28 + 2 * ax;
            float s = gs[base] + gs[base + 1] + gs[base + 28] + gs[base + 29];
            satt[t] = s * (1.f / 256.f);
        }
    } else {
        if (t < HW2) {
            int ay = t / 7, ax = t % 7;
            float s = 0.f;
#pragma unroll
            for (int iy = 0; iy < 4; iy++)
#pragma unroll
                for (int ix = 0; ix < 4; ix++)
                    s += gs[(4 * ay + iy) * 28 + 4 * ax + ix];
            satt[t] = s * (1.f / 1024.f);
        }
    }
    __syncthreads();

    // ---- phase 1: logits for 8 rows per warp ----
    int c0 = chunk * 64 + warp * 8;
    float acc[8];

    if (l == 0) {
        const float* fbase = f0 + ((size_t)(b * C + c0)) * HW0;
        const float4* ap = (const float4*)satt;
#pragma unroll
        for (int j = 0; j < 8; j += 2) {
            const float4* r0 = (const float4*)(fbase + (size_t)j * HW0);
            const float4* r1 = (const float4*)(fbase + (size_t)(j + 1) * HW0);
            float a0 = 0.f, a1 = 0.f;
#pragma unroll
            for (int k = 0; k < 7; k++) {
                int i = lane + 32 * k;
                if (i < HW0 / 4) {
                    float4 v0 = r0[i], v1 = r1[i], a = ap[i];
                    a0 = fmaf(v0.x, a.x, a0); a0 = fmaf(v0.y, a.y, a0);
                    a0 = fmaf(v0.z, a.z, a0); a0 = fmaf(v0.w, a.w, a0);
                    a1 = fmaf(v1.x, a.x, a1); a1 = fmaf(v1.y, a.y, a1);
                    a1 = fmaf(v1.z, a.z, a1); a1 = fmaf(v1.w, a.w, a1);
                }
            }
            acc[j] = a0; acc[j + 1] = a1;
        }
    } else if (l == 1) {
        const float* fbase = f1 + ((size_t)(b * C + c0)) * HW1;
        const float4* ap = (const float4*)satt;
#pragma unroll
        for (int j = 0; j < 8; j += 2) {
            const float4* r0 = (const float4*)(fbase + (size_t)j * HW1);
            const float4* r1 = (const float4*)(fbase + (size_t)(j + 1) * HW1);
            float a0 = 0.f, a1 = 0.f;
#pragma unroll
            for (int k = 0; k < 2; k++) {
                int i = lane + 32 * k;
                if (i < HW1 / 4) {
                    float4 v0 = r0[i], v1 = r1[i], a = ap[i];
                    a0 = fmaf(v0.x, a.x, a0); a0 = fmaf(v0.y, a.y, a0);
                    a0 = fmaf(v0.z, a.z, a0); a0 = fmaf(v0.w, a.w, a0);
                    a1 = fmaf(v1.x, a.x, a1); a1 = fmaf(v1.y, a.y, a1);
                    a1 = fmaf(v1.z, a.z, a1); a1 = fmaf(v1.w, a.w, a1);
                }
            }
            acc[j] = a0; acc[j + 1] = a1;
        }
    } else {
        const float* fbase = f2 + ((size_t)(b * C + c0)) * HW2;
#pragma unroll
        for (int j = 0; j < 8; j += 2) {
            const float* r0 = fbase + (size_t)j * HW2;
            const float* r1 = r0 + HW2;
            float a0 = 0.f, a1 = 0.f;
#pragma unroll
            for (int k = 0; k < 2; k++) {
                int i = lane + 32 * k;
                if (i < HW2) {
                    float a = satt[i];
                    a0 = fmaf(r0[i], a, a0);
                    a1 = fmaf(r1[i], a, a1);
                }
            }
            acc[j] = a0; acc[j + 1] = a1;
        }
    }

#pragma unroll
    for (int j = 0; j < 8; j++) {
#pragma unroll
        for (int o = 16; o > 0; o >>= 1)
            acc[j] += __shfl_xor_sync(0xffffffffu, acc[j], o);
    }
    int base = g * C;
    if (lane == 0) {
        float4 p0 = make_float4(acc[0], acc[1], acc[2], acc[3]);
        float4 p1 = make_float4(acc[4], acc[5], acc[6], acc[7]);
        float4* lp = (float4*)(g_logits + base + c0);
        lp[0] = p0;
        lp[1] = p1;
    }

    // ---- grid barrier (monotonic epoch counter; 384 blocks co-resident) ----
    __threadfence();
    __syncthreads();
    __shared__ unsigned s_target;
    if (t == 0) {
        unsigned old = atomicAdd(&g_bar, 1u);
        s_target = (old / GRID_P + 1u) * GRID_P;
    }
    __syncthreads();
    if (t == 0) {
        while (*((volatile unsigned*)&g_bar) < s_target) __nanosleep(64);
    }
    __syncthreads();
    __threadfence();

    // ---- per-block group softmax reduction (redundant x8, L2-hit) ----
    __shared__ float red[8];
    __shared__ float s_max, s_sum;
    float x0 = g_logits[base + t];
    float x1 = g_logits[base + t + 256];
    float m = fmaxf(x0, x1);
#pragma unroll
    for (int o = 16; o > 0; o >>= 1) m = fmaxf(m, __shfl_xor_sync(0xffffffffu, m, o));
    if (lane == 0) red[warp] = m;
    __syncthreads();
    if (t == 0) {
        float mm = red[0];
#pragma unroll
        for (int i = 1; i < 8; i++) mm = fmaxf(mm, red[i]);
        s_max = mm;
    }
    __syncthreads();
    float smax = s_max;
    float e = __expf(x0 - smax) + __expf(x1 - smax);
#pragma unroll
    for (int o = 16; o > 0; o >>= 1) e += __shfl_xor_sync(0xffffffffu, e, o);
    if (lane == 0) red[warp] = e;
    __syncthreads();
    if (t == 0) {
        float ss = 0.f;
#pragma unroll
        for (int i = 0; i < 8; i++) ss += red[i];
        s_sum = ss;
    }
    __syncthreads();
    float inv = __fdividef(1.f, s_sum);

    // ---- phase 2: scale this warp's 8 rows (feat re-read hits L2) ----
    if (l == 0) {
        const float* fbase = f0 + ((size_t)(b * C + c0)) * HW0;
        float* obase = out + (size_t)b * OUT_ROW + (size_t)c0 * HW0;
#pragma unroll
        for (int j = 0; j < 8; j++) {
            float w = __expf(acc[j] - smax) * inv;
            const float4* src = (const float4*)(fbase + (size_t)j * HW0);
            float4* dst = (float4*)(obase + (size_t)j * HW0);
#pragma unroll
            for (int k = 0; k < 7; k++) {
                int i = lane + 32 * k;
                if (i < HW0 / 4) {
                    float4 v = src[i];
                    v.x *= w; v.y *= w; v.z *= w; v.w *= w;
                    __stcs(&dst[i], v);
                }
            }
        }
    } else if (l == 1) {
        const float* fbase = f1 + ((size_t)(b * C + c0)) * HW1;
        float* obase = out + (size_t)b * OUT_ROW + OUT_OFF1 + (size_t)c0 * HW1;
#pragma unroll
        for (int j = 0; j < 8; j++) {
            float w = __expf(acc[j] - smax) * inv;
            const float4* src = (const float4*)(fbase + (size_t)j * HW1);
            float4* dst = (float4*)(obase + (size_t)j * HW1);
#pragma unroll
            for (int k = 0; k < 2; k++) {
                int i = lane + 32 * k;
                if (i < HW1 / 4) {
                    float4 v = src[i];
                    v.x *= w; v.y *= w; v.z *= w; v.w *= w;
                    __stcs(&dst[i], v);
                }
            }
        }
    } else {
        const float* fbase = f2 + ((size_t)(b * C + c0)) * HW2;
        float* obase = out + (size_t)b * OUT_ROW + OUT_OFF2 + (size_t)c0 * HW2;
#pragma unroll
        for (int j = 0; j < 8; j++) {
            float w = __expf(acc[j] - smax) * inv;
            const float* src = fbase + (size_t)j * HW2;
            float* dst = obase + (size_t)j * HW2;
#pragma unroll
            for (int k = 0; k < 2; k++) {
                int i = lane + 32 * k;
                if (i < HW2) __stcs(&dst[i], src[i] * w);
            }
        }
    }
}

extern "C" void kernel_launch(void* const* d_in, const int* in_sizes, int n_in,
                              void* d_out, int out_size) {
    const float* confs = (const float*)d_in[0];
    const float* boxes = (const float*)d_in[1];
    const float* f0 = (const float*)d_in[2];
    const float* f1 = (const float*)d_in[3];
    const float* f2 = (const float*)d_in[4];
    float* out = (float*)d_out;

    seg_kernel<<<B, 224>>>(boxes);
    tile_kernel<<<dim3(28, B), 256>>>(confs, boxes);
    fused_kernel<<<GRID_P, 256>>>(f0, f1, f2, out);
}